// round 6
// baseline (speedup 1.0000x reference)
#include <cuda_runtime.h>

// Problem constants
#define N_NODES 100000
#define N_EDGES 600000
#define DIM 128

#define TM 64            // rows per tile
#define THREADS 256

// Scratch for segment_sum(edge_attr, dst) -> [N_NODES, DIM]
__device__ float g_agg[(size_t)N_NODES * DIM];

// SMEM layout (floats):
//   s_a : k-major activation tile [256 k][64 rows] = 16384 floats (64KB)
//         (first 128 k-rows reused as s_h [128][64] after GEMM1)
//   s_w : staged weight chunk [64 k][128 cols] row-major = 8192 floats (32KB)
#define SMEM_FLOATS (256 * 64 + 64 * 128)
#define SMEM_BYTES (SMEM_FLOATS * 4)

// Fast exact-enough mish: v * tanh(softplus(v)) = v * n/(n+2), n = e^v*(e^v+2)
__device__ __forceinline__ float mish_f(float v) {
    float t = __expf(v);                 // underflow->0 for very negative v => mish->0 (correct limit)
    float n = t * (t + 2.0f);
    float r = v * __fdividef(n, n + 2.0f);
    return (v > 20.0f) ? v : r;
}

// Packed fp32x2 helpers (Blackwell FFMA2 path)
__device__ __forceinline__ unsigned long long dup_f32x2(float a) {
    unsigned long long r;
    asm("mov.b64 %0, {%1, %1};" : "=l"(r) : "f"(a));
    return r;
}
__device__ __forceinline__ void fma_f32x2(unsigned long long& acc,
                                          unsigned long long a,
                                          unsigned long long b) {
    asm("fma.rn.f32x2 %0, %1, %2, %0;" : "+l"(acc) : "l"(a), "l"(b));
}
__device__ __forceinline__ void unpack_f32x2(unsigned long long v, float& lo, float& hi) {
    asm("mov.b64 {%0, %1}, %2;" : "=f"(lo), "=f"(hi) : "l"(v));
}

// Stage a [64 k][128 col] weight chunk row-major (plain copy, conflict-free)
__device__ __forceinline__ void stage_w(float* s_w, const float* __restrict__ W,
                                        int kbase, int tid) {
    for (int i = tid; i < 2048; i += THREADS) {      // 64 rows x 32 float4
        int r = i >> 5, c4 = i & 31;
        *(float4*)&s_w[r * 128 + c4 * 4] =
            *(const float4*)&W[(kbase + r) * 128 + c4 * 4];
    }
}

// One 64-k chunk of GEMM: acc[2 rows][8 colpairs] += a[k][2 rows] * w[k][16 cols]
// sa: k-major (stride 64), thread rows {2tx, 2tx+1}; s_w row-major, thread cols wy*16..+15.
__device__ __forceinline__ void gemm_chunk(unsigned long long acc[2][8],
                                           const float* sa, const float* s_w,
                                           int tx, int wy) {
#pragma unroll 4
    for (int k = 0; k < 64; ++k) {
        float2 av = *(const float2*)&sa[k * 64 + tx * 2];     // coalesced LDS.64 (2 wavefronts/warp)
        unsigned long long a0 = dup_f32x2(av.x);
        unsigned long long a1 = dup_f32x2(av.y);
        const float* wr = &s_w[k * 128 + wy * 16];            // 4 broadcast LDS.128
        ulonglong2 wA = *(const ulonglong2*)(wr + 0);
        ulonglong2 wB = *(const ulonglong2*)(wr + 4);
        ulonglong2 wC = *(const ulonglong2*)(wr + 8);
        ulonglong2 wD = *(const ulonglong2*)(wr + 12);
        fma_f32x2(acc[0][0], a0, wA.x); fma_f32x2(acc[0][1], a0, wA.y);
        fma_f32x2(acc[0][2], a0, wB.x); fma_f32x2(acc[0][3], a0, wB.y);
        fma_f32x2(acc[0][4], a0, wC.x); fma_f32x2(acc[0][5], a0, wC.y);
        fma_f32x2(acc[0][6], a0, wD.x); fma_f32x2(acc[0][7], a0, wD.y);
        fma_f32x2(acc[1][0], a1, wA.x); fma_f32x2(acc[1][1], a1, wA.y);
        fma_f32x2(acc[1][2], a1, wB.x); fma_f32x2(acc[1][3], a1, wB.y);
        fma_f32x2(acc[1][4], a1, wC.x); fma_f32x2(acc[1][5], a1, wC.y);
        fma_f32x2(acc[1][6], a1, wD.x); fma_f32x2(acc[1][7], a1, wD.y);
    }
}

// Two-layer MLP over a k-major [256][64] tile in s_a.
// h = mish(in @ W1 + b1); out = h @ W2 + b2. Rows >= nvalid are not stored.
__device__ __forceinline__ void mlp_tile(
    float* s_a, float* s_w,
    const float* __restrict__ W1, const float* __restrict__ b1,
    const float* __restrict__ W2, const float* __restrict__ b2,
    float* __restrict__ out, long long rowbase, int nvalid, int tid)
{
    const int tx = tid & 31;          // rows {2tx, 2tx+1}
    const int wy = tid >> 5;          // cols [wy*16, wy*16+16)
    const int r0 = tx * 2;
    const int c0 = wy * 16;

    unsigned long long acc[2][8];
#pragma unroll
    for (int r = 0; r < 2; ++r)
#pragma unroll
        for (int c = 0; c < 8; ++c) acc[r][c] = 0ull;

    // ---- GEMM1: k = 0..255 in 4 chunks ----
    for (int kc = 0; kc < 4; ++kc) {
        __syncthreads();
        stage_w(s_w, W1, kc * 64, tid);
        __syncthreads();
        gemm_chunk(acc, s_a + kc * 64 * 64, s_w, tx, wy);
    }

    __syncthreads();                  // all s_a reads complete before aliasing
    float* s_h = s_a;                 // h tile, k-major [128][64]

    // epilogue 1: bias + mish, store h k-major (STS.64, conflict-free)
#pragma unroll
    for (int cp = 0; cp < 8; ++cp) {
        int c = c0 + cp * 2;
        float x00, x01, x10, x11;
        unpack_f32x2(acc[0][cp], x00, x01);    // row r0:   cols c, c+1
        unpack_f32x2(acc[1][cp], x10, x11);    // row r0+1
        float2 bb = *(const float2*)&b1[c];
        float2 v0 = make_float2(mish_f(x00 + bb.x), mish_f(x10 + bb.x));
        float2 v1 = make_float2(mish_f(x01 + bb.y), mish_f(x11 + bb.y));
        *(float2*)&s_h[(c + 0) * 64 + r0] = v0;
        *(float2*)&s_h[(c + 1) * 64 + r0] = v1;
    }

    unsigned long long acc2[2][8];
#pragma unroll
    for (int r = 0; r < 2; ++r)
#pragma unroll
        for (int c = 0; c < 8; ++c) acc2[r][c] = 0ull;

    // ---- GEMM2: k = 0..127 in 2 chunks (pre-stage barrier orders s_h writes) ----
    for (int kc = 0; kc < 2; ++kc) {
        __syncthreads();
        stage_w(s_w, W2, kc * 64, tid);
        __syncthreads();
        gemm_chunk(acc2, s_h + kc * 64 * 64, s_w, tx, wy);
    }

    // epilogue 2: bias, store rows to global (STG.128 per 16B, rows by lane)
#pragma unroll
    for (int q = 0; q < 4; ++q) {
        float4 bb = *(const float4*)&b2[c0 + q * 4];
        float p0, p1, p2, p3;
        unpack_f32x2(acc2[0][q * 2 + 0], p0, p1);
        unpack_f32x2(acc2[0][q * 2 + 1], p2, p3);
        float4 o0 = make_float4(p0 + bb.x, p1 + bb.y, p2 + bb.z, p3 + bb.w);
        unpack_f32x2(acc2[1][q * 2 + 0], p0, p1);
        unpack_f32x2(acc2[1][q * 2 + 1], p2, p3);
        float4 o1 = make_float4(p0 + bb.x, p1 + bb.y, p2 + bb.z, p3 + bb.w);
        if (r0 < nvalid)
            *(float4*)&out[(rowbase + r0) * 128 + c0 + q * 4] = o0;
        if (r0 + 1 < nvalid)
            *(float4*)&out[(rowbase + r0 + 1) * 128 + c0 + q * 4] = o1;
    }
}

// ---------------- Edge kernel: e = MLP([edge_attr, x[src]+x[dst]]) + scatter agg ----------------
__global__ __launch_bounds__(THREADS, 2)
void edge_kernel(const float* __restrict__ x, const float* __restrict__ ea,
                 const int* __restrict__ eidx,
                 const float* __restrict__ W1, const float* __restrict__ b1,
                 const float* __restrict__ W2, const float* __restrict__ b2,
                 float* __restrict__ e_out, float* __restrict__ agg)
{
    extern __shared__ float sm[];
    float* s_a = sm;                  // [256][64] k-major
    float* s_w = sm + 256 * 64;       // [64][128]
    __shared__ int s_src[TM], s_dst[TM];

    const int tid = threadIdx.x;
    const long long base = (long long)blockIdx.x * TM;    // N_EDGES % TM == 0

    if (tid < TM) {
        s_src[tid] = eidx[base + tid];              // int32 indices
        s_dst[tid] = eidx[N_EDGES + base + tid];
    }
    __syncthreads();

    const int lrow = tid & 63;
    const int kq0  = tid >> 6;                      // 0..3
    const long long e = base + lrow;
    const long long dstoff = (long long)s_dst[lrow] * 128;
    const long long srcoff = (long long)s_src[lrow] * 128;

    // edge_attr -> s_a[k 0..127][row] (transpose; lanes=rows -> conflict-free STS)
    // fused vector scatter-add into agg[dst] from registers
    for (int k4 = kq0; k4 < 32; k4 += 4) {
        float4 v = *(const float4*)&ea[e * 128 + k4 * 4];
        (void)atomicAdd((float4*)&agg[dstoff + k4 * 4], v);
        s_a[(k4 * 4 + 0) * 64 + lrow] = v.x;
        s_a[(k4 * 4 + 1) * 64 + lrow] = v.y;
        s_a[(k4 * 4 + 2) * 64 + lrow] = v.z;
        s_a[(k4 * 4 + 3) * 64 + lrow] = v.w;
    }
    // x[src]+x[dst] -> s_a[k 128..255][row]
    for (int k4 = kq0; k4 < 32; k4 += 4) {
        float4 a = *(const float4*)&x[srcoff + k4 * 4];
        float4 b = *(const float4*)&x[dstoff + k4 * 4];
        s_a[(128 + k4 * 4 + 0) * 64 + lrow] = a.x + b.x;
        s_a[(128 + k4 * 4 + 1) * 64 + lrow] = a.y + b.y;
        s_a[(128 + k4 * 4 + 2) * 64 + lrow] = a.z + b.z;
        s_a[(128 + k4 * 4 + 3) * 64 + lrow] = a.w + b.w;
    }
    // visibility of s_a handled by the first __syncthreads inside mlp_tile

    mlp_tile(s_a, s_w, W1, b1, W2, b2, e_out, base, TM, tid);
}

// ---------------- Node kernel: x_out = MLP([x, agg]) ----------------
__global__ __launch_bounds__(THREADS, 2)
void node_kernel(const float* __restrict__ x, const float* __restrict__ agg,
                 const float* __restrict__ W1, const float* __restrict__ b1,
                 const float* __restrict__ W2, const float* __restrict__ b2,
                 float* __restrict__ x_out)
{
    extern __shared__ float sm[];
    float* s_a = sm;
    float* s_w = sm + 256 * 64;

    const int tid = threadIdx.x;
    const long long base = (long long)blockIdx.x * TM;
    const int nvalid = (int)min((long long)TM, (long long)N_NODES - base);

    const int lrow = tid & 63;
    const int kq0  = tid >> 6;
    const bool ok  = lrow < nvalid;
    const long long n = base + lrow;

    for (int k4 = kq0; k4 < 32; k4 += 4) {
        float4 v = ok ? *(const float4*)&x[n * 128 + k4 * 4]
                      : make_float4(0.f, 0.f, 0.f, 0.f);
        s_a[(k4 * 4 + 0) * 64 + lrow] = v.x;
        s_a[(k4 * 4 + 1) * 64 + lrow] = v.y;
        s_a[(k4 * 4 + 2) * 64 + lrow] = v.z;
        s_a[(k4 * 4 + 3) * 64 + lrow] = v.w;
    }
    for (int k4 = kq0; k4 < 32; k4 += 4) {
        float4 g = ok ? *(const float4*)&agg[n * 128 + k4 * 4]
                      : make_float4(0.f, 0.f, 0.f, 0.f);
        s_a[(128 + k4 * 4 + 0) * 64 + lrow] = g.x;
        s_a[(128 + k4 * 4 + 1) * 64 + lrow] = g.y;
        s_a[(128 + k4 * 4 + 2) * 64 + lrow] = g.z;
        s_a[(128 + k4 * 4 + 3) * 64 + lrow] = g.w;
    }

    mlp_tile(s_a, s_w, W1, b1, W2, b2, x_out, base, nvalid, tid);
}

extern "C" void kernel_launch(void* const* d_in, const int* in_sizes, int n_in,
                              void* d_out, int out_size)
{
    const float* x    = (const float*)d_in[0];
    const float* ea   = (const float*)d_in[1];
    const int*   eidx = (const int*)d_in[2];      // int32 (JAX x64 disabled)
    const float* eW1  = (const float*)d_in[3];
    const float* eb1  = (const float*)d_in[4];
    const float* eW2  = (const float*)d_in[5];
    const float* eb2  = (const float*)d_in[6];
    const float* nW1  = (const float*)d_in[7];
    const float* nb1  = (const float*)d_in[8];
    const float* nW2  = (const float*)d_in[9];
    const float* nb2  = (const float*)d_in[10];

    float* out   = (float*)d_out;
    float* x_out = out;                                 // [N_NODES,128] first (tuple order)
    float* e_out = out + (long long)N_NODES * DIM;      // then e [N_EDGES,128]

    void* aggp = nullptr;
    cudaGetSymbolAddress(&aggp, g_agg);
    cudaMemsetAsync(aggp, 0, sizeof(float) * (size_t)N_NODES * DIM);

    cudaFuncSetAttribute(edge_kernel, cudaFuncAttributeMaxDynamicSharedMemorySize, SMEM_BYTES);
    cudaFuncSetAttribute(node_kernel, cudaFuncAttributeMaxDynamicSharedMemorySize, SMEM_BYTES);

    int edge_blocks = N_EDGES / TM;                     // 9375
    int node_blocks = (N_NODES + TM - 1) / TM;          // 1563

    edge_kernel<<<edge_blocks, THREADS, SMEM_BYTES>>>(
        x, ea, eidx, eW1, eb1, eW2, eb2, e_out, (float*)aggp);
    node_kernel<<<node_blocks, THREADS, SMEM_BYTES>>>(
        x, (const float*)aggp, nW1, nb1, nW2, nb2, x_out);
}